// round 1
// baseline (speedup 1.0000x reference)
#include <cuda_runtime.h>
#include <cuda_bf16.h>
#include <cstdint>

// Problem constants (fixed by the dataset)
#define BB   1024
#define TT   256
#define INDIM 128
#define HH   128
#define GG   384      // 3*H
#define HOR  24

// ---------------- scratch (device globals; no allocations allowed) ----------
__device__ float g_gx[(size_t)TT * BB * GG];        // 384 MB: x@w_i + b, layout [t][b][g]
__device__ float g_W2[(size_t)TT * HH * HOR];       // 3 MB:  folded mlp_w@fc_w_t@out_w, [t][i][p]
__device__ float g_bias_part[TT * HOR];             // per-t bias partials (deterministic reduce)
__device__ float g_final_bias[HOR];

// ---------------- activation helpers ----------------------------------------
__device__ __forceinline__ float sigmoid_f(float x) {
    return 1.0f / (1.0f + __expf(-x));
}
__device__ __forceinline__ float tanh_f(float x) {
    // accurate, overflow-safe: tanh(x) = sign(x) * (1 - 2/(e^{2|x|}+1))
    float ax = fabsf(x);
    float e  = __expf(2.0f * ax);          // -> inf for large ax, 2/(e+1) -> 0, ok
    float r  = 1.0f - 2.0f / (e + 1.0f);
    return copysignf(r, x);
}

// ============================================================================
// Kernel 1: fold  W2_t = mlp_w @ (fc_w_t @ out_w)   and  bias partial per t.
// grid = 256 (one CTA per t), 256 threads, 64 KB dyn smem.
// ============================================================================
__global__ void __launch_bounds__(256) w2_kernel(
    const float* __restrict__ mlp_w,   // [128,512]
    const float* __restrict__ mlp_b,   // [512]
    const float* __restrict__ fc_w,    // [131072,128]
    const float* __restrict__ out_w)   // [128,24]
{
    extern __shared__ float sm[];
    float* ows    = sm;                 // 128*24 = 3072
    float* P      = sm + 3072;          // 512*24 = 12288
    float* rowbuf = sm + 3072 + 12288;  // 8*128  = 1024
    const int tid  = threadIdx.x;
    const int t    = blockIdx.x;
    const int warp = tid >> 5;
    const int lane = tid & 31;

    for (int i = tid; i < HH * HOR; i += 256) ows[i] = out_w[i];
    __syncthreads();

    // P[j][p] = fc_w[t*512+j][:] . out_w[:][p]
    const float* fcb = fc_w + (size_t)t * 512 * HH;
    for (int j = warp; j < 512; j += 8) {
        float4 v = ((const float4*)(fcb + (size_t)j * HH))[lane];
        ((float4*)(rowbuf + warp * 128))[lane] = v;
        __syncwarp();
        if (lane < HOR) {
            const float* rb = rowbuf + warp * 128;
            float acc = 0.0f;
            #pragma unroll 4
            for (int k = 0; k < 128; k++) acc = fmaf(rb[k], ows[k * HOR + lane], acc);
            P[j * HOR + lane] = acc;
        }
        __syncwarp();
    }
    __syncthreads();

    // bias partial: (mlp_b @ P_t)[p]  -> g_bias_part[t][p]  (no atomics)
    if (warp == 0 && lane < HOR) {
        float acc = 0.0f;
        for (int j = 0; j < 512; j++) acc = fmaf(mlp_b[j], P[j * HOR + lane], acc);
        g_bias_part[t * HOR + lane] = acc;
    }

    // W2_t[i][p] = mlp_w[i][:] . P[:][p]
    const int i  = tid & 127;
    const int p0 = (tid >> 7) * 12;
    float acc[12];
    #pragma unroll
    for (int q = 0; q < 12; q++) acc[q] = 0.0f;
    const float* mw = mlp_w + (size_t)i * 512;
    for (int j = 0; j < 512; j++) {
        float m = mw[j];
        const float* pr = P + j * HOR + p0;
        #pragma unroll
        for (int q = 0; q < 12; q++) acc[q] = fmaf(m, pr[q], acc[q]);
    }
    float* dst = g_W2 + ((size_t)t * HH + i) * HOR + p0;
    #pragma unroll
    for (int q = 0; q < 12; q++) dst[q] = acc[q];
}

// ============================================================================
// Kernel 2: final bias = sum_t bias_part + fc_b@out_w + out_b
// ============================================================================
__global__ void bias_final_kernel(const float* __restrict__ fc_b,
                                  const float* __restrict__ out_w,
                                  const float* __restrict__ out_b)
{
    int p = threadIdx.x;
    if (p >= HOR) return;
    float s = out_b[p];
    for (int t = 0; t < TT; t++) s += g_bias_part[t * HOR + p];
    for (int o = 0; o < HH; o++) s = fmaf(fc_b[o], out_w[o * HOR + p], s);
    g_final_bias[p] = s;
}

// ============================================================================
// Kernel 3: gx[t][b][g] = x[b][t][:] @ w_i[:,g] + b[g]
// CTA tile: 32 rows (m = b*256+t) x 384 cols. 8192 CTAs, 256 threads.
// smem: xT [128][36] transposed tile + full w_i + bias.
// ============================================================================
#define XT_LD 36
__global__ void __launch_bounds__(256, 1) gx_kernel(
    const float* __restrict__ x,     // [B][T][128]
    const float* __restrict__ w_i,   // [128][384]
    const float* __restrict__ bvec)  // [384]
{
    extern __shared__ float sm[];
    float* xT = sm;                        // 128*36 = 4608
    float* ws = sm + 128 * XT_LD;          // 49152
    float* bs = ws + 128 * GG;             // 384
    const int tid = threadIdx.x;
    const int m0  = blockIdx.x * 32;

    // stage x tile transposed: xT[k][m]
    {
        int row = tid >> 3;              // 0..31
        int k0  = (tid & 7) * 16;        // 0..112
        const float* xrow = x + (size_t)(m0 + row) * INDIM;
        #pragma unroll
        for (int u = 0; u < 4; u++) {
            float4 v = *(const float4*)(xrow + k0 + u * 4);
            int k = k0 + u * 4;
            xT[(k + 0) * XT_LD + row] = v.x;
            xT[(k + 1) * XT_LD + row] = v.y;
            xT[(k + 2) * XT_LD + row] = v.z;
            xT[(k + 3) * XT_LD + row] = v.w;
        }
    }
    // stage w_i + bias
    {
        const float4* src = (const float4*)w_i;
        float4* dst = (float4*)ws;
        for (int idx = tid; idx < (128 * GG) / 4; idx += 256) dst[idx] = src[idx];
        for (int idx = tid; idx < GG; idx += 256) bs[idx] = bvec[idx];
    }
    __syncthreads();

    // per-thread tile: 4 rows x 12 cols
    const int g0  = (tid & 31) * 12;
    const int mr0 = (tid >> 5) * 4;
    float acc[4][12];
    #pragma unroll
    for (int r = 0; r < 4; r++)
        #pragma unroll
        for (int q = 0; q < 12; q++) acc[r][q] = 0.0f;

    #pragma unroll 2
    for (int k = 0; k < 128; k++) {
        float4 xv  = *(const float4*)&xT[k * XT_LD + mr0];
        const float* wr = &ws[k * GG + g0];
        float4 w0 = *(const float4*)(wr);
        float4 w1 = *(const float4*)(wr + 4);
        float4 w2 = *(const float4*)(wr + 8);
        float wv[12] = {w0.x,w0.y,w0.z,w0.w, w1.x,w1.y,w1.z,w1.w, w2.x,w2.y,w2.z,w2.w};
        float xr[4]  = {xv.x, xv.y, xv.z, xv.w};
        #pragma unroll
        for (int r = 0; r < 4; r++)
            #pragma unroll
            for (int q = 0; q < 12; q++)
                acc[r][q] = fmaf(xr[r], wv[q], acc[r][q]);
    }

    #pragma unroll
    for (int r = 0; r < 4; r++) {
        int m  = m0 + mr0 + r;
        int bb = m >> 8;         // b
        int tt = m & 255;        // t
        float* dst = g_gx + ((size_t)tt * BB + bb) * GG + g0;
        #pragma unroll
        for (int q = 0; q < 12; q += 4) {
            float4 o;
            o.x = acc[r][q + 0] + bs[g0 + q + 0];
            o.y = acc[r][q + 1] + bs[g0 + q + 1];
            o.z = acc[r][q + 2] + bs[g0 + q + 2];
            o.w = acc[r][q + 3] + bs[g0 + q + 3];
            *(float4*)(dst + q) = o;
        }
    }
}

// ============================================================================
// Kernel 4: persistent recurrence. 128 CTAs x 256 threads; CTA owns 8 batch
// rows for all 256 steps. w_h resident in smem. Fused out += h_t @ W2_t.
// ============================================================================
__global__ void __launch_bounds__(256, 1) rec_kernel(
    const float* __restrict__ w_h,   // [128][384]
    float* __restrict__ out)         // [1024][24]
{
    extern __shared__ float sm[];
    float* whs = sm;                  // 49152
    float* hT  = whs + 128 * GG;      // [k][r] 128*8 = 1024
    float* rhT = hT + 1024;           // 1024
    float* zs  = rhT + 1024;          // [r][col] 8*128 = 1024
    float* W2s = zs + 1024;           // 128*24 = 3072

    const int tid = threadIdx.x;
    const int b0  = blockIdx.x * 8;

    {
        const float4* src = (const float4*)w_h;
        float4* dst = (float4*)whs;
        for (int idx = tid; idx < (128 * GG) / 4; idx += 256) dst[idx] = src[idx];
        for (int idx = tid; idx < 1024; idx += 256) hT[idx] = 0.0f;
    }
    const int  orow    = tid / HOR;
    const int  op      = tid - orow * HOR;
    const bool has_out = (tid < 8 * HOR);
    float oacc = 0.0f;
    __syncthreads();

    for (int t = 0; t < TT; t++) {
        const float* gxt = g_gx + ((size_t)t * BB + b0) * GG;

        // stage W2_t (last reader of previous W2s finished at prior barrier)
        {
            const float* src = g_W2 + (size_t)t * HH * HOR;
            for (int idx = tid; idx < HH * HOR; idx += 256) W2s[idx] = src[idx];
        }

        // ---- phase 1: zr pre-activations, col = tid (0..255), all 8 rows ----
        {
            const int col = tid;
            float a8[8];
            #pragma unroll
            for (int r = 0; r < 8; r++) a8[r] = 0.0f;
            #pragma unroll 4
            for (int k = 0; k < 128; k++) {
                float4 h0 = *(const float4*)&hT[k * 8];
                float4 h1 = *(const float4*)&hT[k * 8 + 4];
                float  w  = whs[k * GG + col];
                a8[0] = fmaf(h0.x, w, a8[0]);
                a8[1] = fmaf(h0.y, w, a8[1]);
                a8[2] = fmaf(h0.z, w, a8[2]);
                a8[3] = fmaf(h0.w, w, a8[3]);
                a8[4] = fmaf(h1.x, w, a8[4]);
                a8[5] = fmaf(h1.y, w, a8[5]);
                a8[6] = fmaf(h1.z, w, a8[6]);
                a8[7] = fmaf(h1.w, w, a8[7]);
            }
            float gval[8];
            #pragma unroll
            for (int r = 0; r < 8; r++)
                gval[r] = sigmoid_f(a8[r] + gxt[r * GG + col]);
            if (col < 128) {            // z gate
                #pragma unroll
                for (int r = 0; r < 8; r++) zs[r * 128 + col] = gval[r];
            } else {                    // r gate -> rh = r .* h
                int j = col - 128;
                #pragma unroll
                for (int r = 0; r < 8; r++) rhT[j * 8 + r] = gval[r] * hT[j * 8 + r];
            }
        }
        __syncthreads();

        // ---- phase 2: a = tanh(gx_a + rh @ w_h_a), h update -----------------
        {
            const int c2  = tid & 127;
            const int r0v = (tid >> 7) * 4;
            float aa[4] = {0.0f, 0.0f, 0.0f, 0.0f};
            #pragma unroll 4
            for (int k = 0; k < 128; k++) {
                float4 rv = *(const float4*)&rhT[k * 8 + r0v];
                float  w  = whs[k * GG + 256 + c2];
                aa[0] = fmaf(rv.x, w, aa[0]);
                aa[1] = fmaf(rv.y, w, aa[1]);
                aa[2] = fmaf(rv.z, w, aa[2]);
                aa[3] = fmaf(rv.w, w, aa[3]);
            }
            #pragma unroll
            for (int q = 0; q < 4; q++) {
                int   r    = r0v + q;
                float av   = tanh_f(aa[q] + gxt[r * GG + 256 + c2]);
                float z    = zs[r * 128 + c2];
                float hold = hT[c2 * 8 + r];
                hT[c2 * 8 + r] = fmaf(z, av - hold, hold);   // (1-z)h + z*a
            }
        }
        __syncthreads();

        // ---- fused output projection: out_acc += h_t @ W2_t -----------------
        if (has_out) {
            float s = 0.0f;
            #pragma unroll 4
            for (int j = 0; j < 128; j++)
                s = fmaf(hT[j * 8 + orow], W2s[j * HOR + op], s);
            oacc += s;
        }
        __syncthreads();
    }

    if (has_out)
        out[(size_t)(b0 + orow) * HOR + op] = oacc + g_final_bias[op];
}

// ============================================================================
// launch
// ============================================================================
extern "C" void kernel_launch(void* const* d_in, const int* in_sizes, int n_in,
                              void* d_out, int out_size)
{
    const float* x     = (const float*)d_in[0];
    const float* w_i   = (const float*)d_in[1];
    const float* w_h   = (const float*)d_in[2];
    const float* bvec  = (const float*)d_in[3];
    const float* mlp_w = (const float*)d_in[4];
    const float* mlp_b = (const float*)d_in[5];
    const float* fc_w  = (const float*)d_in[6];
    const float* fc_b  = (const float*)d_in[7];
    const float* out_w = (const float*)d_in[8];
    const float* out_b = (const float*)d_in[9];
    float* out = (float*)d_out;

    const int smem_w2  = (3072 + 12288 + 1024) * 4;                 // 65536
    const int smem_gx  = (128 * XT_LD + 128 * GG + GG) * 4;         // 216576
    const int smem_rec = (128 * GG + 1024 + 1024 + 1024 + 3072) * 4;// 221184

    cudaFuncSetAttribute(w2_kernel,  cudaFuncAttributeMaxDynamicSharedMemorySize, smem_w2);
    cudaFuncSetAttribute(gx_kernel,  cudaFuncAttributeMaxDynamicSharedMemorySize, smem_gx);
    cudaFuncSetAttribute(rec_kernel, cudaFuncAttributeMaxDynamicSharedMemorySize, smem_rec);

    w2_kernel<<<TT, 256, smem_w2>>>(mlp_w, mlp_b, fc_w, out_w);
    bias_final_kernel<<<1, 32>>>(fc_b, out_w, out_b);
    gx_kernel<<<(BB * TT) / 32, 256, smem_gx>>>(x, w_i, bvec);
    rec_kernel<<<BB / 8, 256, smem_rec>>>(w_h, out);
}

// round 2
// speedup vs baseline: 1.0150x; 1.0150x over previous
#include <cuda_runtime.h>
#include <cuda_bf16.h>
#include <cstdint>

// Problem constants (fixed by the dataset)
#define BB   1024
#define TT   256
#define INDIM 128
#define HH   128
#define GG   384      // 3*H
#define HOR  24

// ---------------- scratch (device globals; no allocations allowed) ----------
__device__ float g_gx[(size_t)TT * BB * GG];        // 384 MB: x@w_i + b, layout [t][b][g]
__device__ float g_W2[(size_t)TT * HH * HOR];       // 3 MB:  folded mlp_w@fc_w_t@out_w, [t][i][p]
__device__ float g_bias_part[TT * HOR];             // per-t bias partials (deterministic reduce)
__device__ float g_final_bias[HOR];

// ---------------- activation helpers ----------------------------------------
__device__ __forceinline__ float sigmoid_f(float x) {
    return 1.0f / (1.0f + __expf(-x));
}
__device__ __forceinline__ float tanh_f(float x) {
    // accurate, overflow-safe: tanh(x) = sign(x) * (1 - 2/(e^{2|x|}+1))
    float ax = fabsf(x);
    float e  = __expf(2.0f * ax);          // -> inf for large ax, 2/(e+1) -> 0, ok
    float r  = 1.0f - 2.0f / (e + 1.0f);
    return copysignf(r, x);
}

// ============================================================================
// Kernel 1: fold  W2_t = mlp_w @ (fc_w_t @ out_w)   and  bias partial per t.
// grid = 256 (one CTA per t), 256 threads, 64 KB dyn smem.
// ============================================================================
__global__ void __launch_bounds__(256) w2_kernel(
    const float* __restrict__ mlp_w,   // [128,512]
    const float* __restrict__ mlp_b,   // [512]
    const float* __restrict__ fc_w,    // [131072,128]
    const float* __restrict__ out_w)   // [128,24]
{
    extern __shared__ float sm[];
    float* ows    = sm;                 // 128*24 = 3072
    float* P      = sm + 3072;          // 512*24 = 12288
    float* rowbuf = sm + 3072 + 12288;  // 8*128  = 1024
    const int tid  = threadIdx.x;
    const int t    = blockIdx.x;
    const int warp = tid >> 5;
    const int lane = tid & 31;

    for (int i = tid; i < HH * HOR; i += 256) ows[i] = out_w[i];
    __syncthreads();

    // P[j][p] = fc_w[t*512+j][:] . out_w[:][p]
    const float* fcb = fc_w + (size_t)t * 512 * HH;
    for (int j = warp; j < 512; j += 8) {
        float4 v = ((const float4*)(fcb + (size_t)j * HH))[lane];
        ((float4*)(rowbuf + warp * 128))[lane] = v;
        __syncwarp();
        if (lane < HOR) {
            const float* rb = rowbuf + warp * 128;
            float acc = 0.0f;
            #pragma unroll 4
            for (int k = 0; k < 128; k++) acc = fmaf(rb[k], ows[k * HOR + lane], acc);
            P[j * HOR + lane] = acc;
        }
        __syncwarp();
    }
    __syncthreads();

    // bias partial: (mlp_b @ P_t)[p]  -> g_bias_part[t][p]  (no atomics)
    if (warp == 0 && lane < HOR) {
        float acc = 0.0f;
        for (int j = 0; j < 512; j++) acc = fmaf(mlp_b[j], P[j * HOR + lane], acc);
        g_bias_part[t * HOR + lane] = acc;
    }

    // W2_t[i][p] = mlp_w[i][:] . P[:][p]
    const int i  = tid & 127;
    const int p0 = (tid >> 7) * 12;
    float acc[12];
    #pragma unroll
    for (int q = 0; q < 12; q++) acc[q] = 0.0f;
    const float* mw = mlp_w + (size_t)i * 512;
    for (int j = 0; j < 512; j++) {
        float m = mw[j];
        const float* pr = P + j * HOR + p0;
        #pragma unroll
        for (int q = 0; q < 12; q++) acc[q] = fmaf(m, pr[q], acc[q]);
    }
    float* dst = g_W2 + ((size_t)t * HH + i) * HOR + p0;
    #pragma unroll
    for (int q = 0; q < 12; q++) dst[q] = acc[q];
}

// ============================================================================
// Kernel 2: final bias = sum_t bias_part + fc_b@out_w + out_b
// ============================================================================
__global__ void bias_final_kernel(const float* __restrict__ fc_b,
                                  const float* __restrict__ out_w,
                                  const float* __restrict__ out_b)
{
    int p = threadIdx.x;
    if (p >= HOR) return;
    float s = out_b[p];
    for (int t = 0; t < TT; t++) s += g_bias_part[t * HOR + p];
    for (int o = 0; o < HH; o++) s = fmaf(fc_b[o], out_w[o * HOR + p], s);
    g_final_bias[p] = s;
}

// ============================================================================
// Kernel 3: gx[t][b][g] = x[b][t][:] @ w_i[:,g] + b[g]
// CTA tile: 32 rows (m = b*256+t) x 384 cols. 8192 CTAs, 256 threads.
// smem: xT [128][36] transposed tile + full w_i + bias.
// ============================================================================
#define XT_LD 36
__global__ void __launch_bounds__(256, 1) gx_kernel(
    const float* __restrict__ x,     // [B][T][128]
    const float* __restrict__ w_i,   // [128][384]
    const float* __restrict__ bvec)  // [384]
{
    extern __shared__ float sm[];
    float* xT = sm;                        // 128*36 = 4608
    float* ws = sm + 128 * XT_LD;          // 49152
    float* bs = ws + 128 * GG;             // 384
    const int tid = threadIdx.x;
    const int m0  = blockIdx.x * 32;

    // stage x tile transposed: xT[k][m]
    {
        int row = tid >> 3;              // 0..31
        int k0  = (tid & 7) * 16;        // 0..112
        const float* xrow = x + (size_t)(m0 + row) * INDIM;
        #pragma unroll
        for (int u = 0; u < 4; u++) {
            float4 v = *(const float4*)(xrow + k0 + u * 4);
            int k = k0 + u * 4;
            xT[(k + 0) * XT_LD + row] = v.x;
            xT[(k + 1) * XT_LD + row] = v.y;
            xT[(k + 2) * XT_LD + row] = v.z;
            xT[(k + 3) * XT_LD + row] = v.w;
        }
    }
    // stage w_i + bias
    {
        const float4* src = (const float4*)w_i;
        float4* dst = (float4*)ws;
        for (int idx = tid; idx < (128 * GG) / 4; idx += 256) dst[idx] = src[idx];
        for (int idx = tid; idx < GG; idx += 256) bs[idx] = bvec[idx];
    }
    __syncthreads();

    // per-thread tile: 4 rows x 12 cols
    const int g0  = (tid & 31) * 12;
    const int mr0 = (tid >> 5) * 4;
    float acc[4][12];
    #pragma unroll
    for (int r = 0; r < 4; r++)
        #pragma unroll
        for (int q = 0; q < 12; q++) acc[r][q] = 0.0f;

    #pragma unroll 2
    for (int k = 0; k < 128; k++) {
        float4 xv  = *(const float4*)&xT[k * XT_LD + mr0];
        const float* wr = &ws[k * GG + g0];
        float4 w0 = *(const float4*)(wr);
        float4 w1 = *(const float4*)(wr + 4);
        float4 w2 = *(const float4*)(wr + 8);
        float wv[12] = {w0.x,w0.y,w0.z,w0.w, w1.x,w1.y,w1.z,w1.w, w2.x,w2.y,w2.z,w2.w};
        float xr[4]  = {xv.x, xv.y, xv.z, xv.w};
        #pragma unroll
        for (int r = 0; r < 4; r++)
            #pragma unroll
            for (int q = 0; q < 12; q++)
                acc[r][q] = fmaf(xr[r], wv[q], acc[r][q]);
    }

    #pragma unroll
    for (int r = 0; r < 4; r++) {
        int m  = m0 + mr0 + r;
        int bb = m >> 8;         // b
        int tt = m & 255;        // t
        float* dst = g_gx + ((size_t)tt * BB + bb) * GG + g0;
        #pragma unroll
        for (int q = 0; q < 12; q += 4) {
            float4 o;
            o.x = acc[r][q + 0] + bs[g0 + q + 0];
            o.y = acc[r][q + 1] + bs[g0 + q + 1];
            o.z = acc[r][q + 2] + bs[g0 + q + 2];
            o.w = acc[r][q + 3] + bs[g0 + q + 3];
            *(float4*)(dst + q) = o;
        }
    }
}

// ============================================================================
// Kernel 4: persistent recurrence. 128 CTAs x 256 threads; CTA owns 8 batch
// rows for all 256 steps. w_h resident in smem. Fused out += h_t @ W2_t.
// ============================================================================
__global__ void __launch_bounds__(256, 1) rec_kernel(
    const float* __restrict__ w_h,   // [128][384]
    float* __restrict__ out)         // [1024][24]
{
    extern __shared__ float sm[];
    float* whs = sm;                  // 49152
    float* hT  = whs + 128 * GG;      // [k][r] 128*8 = 1024
    float* rhT = hT + 1024;           // 1024
    float* zs  = rhT + 1024;          // [r][col] 8*128 = 1024
    float* W2s = zs + 1024;           // 128*24 = 3072

    const int tid = threadIdx.x;
    const int b0  = blockIdx.x * 8;

    {
        const float4* src = (const float4*)w_h;
        float4* dst = (float4*)whs;
        for (int idx = tid; idx < (128 * GG) / 4; idx += 256) dst[idx] = src[idx];
        for (int idx = tid; idx < 1024; idx += 256) hT[idx] = 0.0f;
    }
    const int  orow    = tid / HOR;
    const int  op      = tid - orow * HOR;
    const bool has_out = (tid < 8 * HOR);
    float oacc = 0.0f;
    __syncthreads();

    for (int t = 0; t < TT; t++) {
        const float* gxt = g_gx + ((size_t)t * BB + b0) * GG;

        // stage W2_t (last reader of previous W2s finished at prior barrier)
        {
            const float* src = g_W2 + (size_t)t * HH * HOR;
            for (int idx = tid; idx < HH * HOR; idx += 256) W2s[idx] = src[idx];
        }

        // ---- phase 1: zr pre-activations, col = tid (0..255), all 8 rows ----
        {
            const int col = tid;
            float a8[8];
            #pragma unroll
            for (int r = 0; r < 8; r++) a8[r] = 0.0f;
            #pragma unroll 4
            for (int k = 0; k < 128; k++) {
                float4 h0 = *(const float4*)&hT[k * 8];
                float4 h1 = *(const float4*)&hT[k * 8 + 4];
                float  w  = whs[k * GG + col];
                a8[0] = fmaf(h0.x, w, a8[0]);
                a8[1] = fmaf(h0.y, w, a8[1]);
                a8[2] = fmaf(h0.z, w, a8[2]);
                a8[3] = fmaf(h0.w, w, a8[3]);
                a8[4] = fmaf(h1.x, w, a8[4]);
                a8[5] = fmaf(h1.y, w, a8[5]);
                a8[6] = fmaf(h1.z, w, a8[6]);
                a8[7] = fmaf(h1.w, w, a8[7]);
            }
            float gval[8];
            #pragma unroll
            for (int r = 0; r < 8; r++)
                gval[r] = sigmoid_f(a8[r] + gxt[r * GG + col]);
            if (col < 128) {            // z gate
                #pragma unroll
                for (int r = 0; r < 8; r++) zs[r * 128 + col] = gval[r];
            } else {                    // r gate -> rh = r .* h
                int j = col - 128;
                #pragma unroll
                for (int r = 0; r < 8; r++) rhT[j * 8 + r] = gval[r] * hT[j * 8 + r];
            }
        }
        __syncthreads();

        // ---- phase 2: a = tanh(gx_a + rh @ w_h_a), h update -----------------
        {
            const int c2  = tid & 127;
            const int r0v = (tid >> 7) * 4;
            float aa[4] = {0.0f, 0.0f, 0.0f, 0.0f};
            #pragma unroll 4
            for (int k = 0; k < 128; k++) {
                float4 rv = *(const float4*)&rhT[k * 8 + r0v];
                float  w  = whs[k * GG + 256 + c2];
                aa[0] = fmaf(rv.x, w, aa[0]);
                aa[1] = fmaf(rv.y, w, aa[1]);
                aa[2] = fmaf(rv.z, w, aa[2]);
                aa[3] = fmaf(rv.w, w, aa[3]);
            }
            #pragma unroll
            for (int q = 0; q < 4; q++) {
                int   r    = r0v + q;
                float av   = tanh_f(aa[q] + gxt[r * GG + 256 + c2]);
                float z    = zs[r * 128 + c2];
                float hold = hT[c2 * 8 + r];
                hT[c2 * 8 + r] = fmaf(z, av - hold, hold);   // (1-z)h + z*a
            }
        }
        __syncthreads();

        // ---- fused output projection: out_acc += h_t @ W2_t -----------------
        if (has_out) {
            float s = 0.0f;
            #pragma unroll 4
            for (int j = 0; j < 128; j++)
                s = fmaf(hT[j * 8 + orow], W2s[j * HOR + op], s);
            oacc += s;
        }
        __syncthreads();
    }

    if (has_out)
        out[(size_t)(b0 + orow) * HOR + op] = oacc + g_final_bias[op];
}

// ============================================================================
// launch
// ============================================================================
extern "C" void kernel_launch(void* const* d_in, const int* in_sizes, int n_in,
                              void* d_out, int out_size)
{
    const float* x     = (const float*)d_in[0];
    const float* w_i   = (const float*)d_in[1];
    const float* w_h   = (const float*)d_in[2];
    const float* bvec  = (const float*)d_in[3];
    const float* mlp_w = (const float*)d_in[4];
    const float* mlp_b = (const float*)d_in[5];
    const float* fc_w  = (const float*)d_in[6];
    const float* fc_b  = (const float*)d_in[7];
    const float* out_w = (const float*)d_in[8];
    const float* out_b = (const float*)d_in[9];
    float* out = (float*)d_out;

    const int smem_w2  = (3072 + 12288 + 1024) * 4;                 // 65536
    const int smem_gx  = (128 * XT_LD + 128 * GG + GG) * 4;         // 216576
    const int smem_rec = (128 * GG + 1024 + 1024 + 1024 + 3072) * 4;// 221184

    cudaFuncSetAttribute(w2_kernel,  cudaFuncAttributeMaxDynamicSharedMemorySize, smem_w2);
    cudaFuncSetAttribute(gx_kernel,  cudaFuncAttributeMaxDynamicSharedMemorySize, smem_gx);
    cudaFuncSetAttribute(rec_kernel, cudaFuncAttributeMaxDynamicSharedMemorySize, smem_rec);

    w2_kernel<<<TT, 256, smem_w2>>>(mlp_w, mlp_b, fc_w, out_w);
    bias_final_kernel<<<1, 32>>>(fc_b, out_w, out_b);
    gx_kernel<<<(BB * TT) / 32, 256, smem_gx>>>(x, w_i, bvec);
    rec_kernel<<<BB / 8, 256, smem_rec>>>(w_h, out);
}

// round 3
// speedup vs baseline: 1.6448x; 1.6204x over previous
#include <cuda_runtime.h>
#include <cuda_bf16.h>
#include <cstdint>

// Problem constants (fixed by the dataset)
#define BB   1024
#define TT   256
#define INDIM 128
#define HH   128
#define GG   384      // 3*H
#define HOR  24

// ---------------- scratch (device globals; no allocations allowed) ----------
__device__ float g_gx[(size_t)TT * BB * GG];        // 384 MB: x@w_i + b, layout [t][b][g]
__device__ float g_W2[(size_t)TT * HH * HOR];       // 3 MB:  folded mlp_w@fc_w_t@out_w, [t][i][p]
__device__ float g_bias_part[TT * HOR];             // per-t bias partials (deterministic reduce)
__device__ float g_final_bias[HOR];

// ---------------- activation helpers ----------------------------------------
__device__ __forceinline__ float sigmoid_f(float x) {
    return 1.0f / (1.0f + __expf(-x));
}
__device__ __forceinline__ float tanh_f(float x) {
    float ax = fabsf(x);
    float e  = __expf(2.0f * ax);
    float r  = 1.0f - 2.0f / (e + 1.0f);
    return copysignf(r, x);
}

// ============================================================================
// Kernel 1: fold  W2_t = mlp_w @ (fc_w_t @ out_w)   and  bias partial per t.
// grid = 256 (one CTA per t), 256 threads, 64 KB dyn smem.  (unchanged)
// ============================================================================
__global__ void __launch_bounds__(256) w2_kernel(
    const float* __restrict__ mlp_w,   // [128,512]
    const float* __restrict__ mlp_b,   // [512]
    const float* __restrict__ fc_w,    // [131072,128]
    const float* __restrict__ out_w)   // [128,24]
{
    extern __shared__ float sm[];
    float* ows    = sm;                 // 128*24 = 3072
    float* P      = sm + 3072;          // 512*24 = 12288
    float* rowbuf = sm + 3072 + 12288;  // 8*128  = 1024
    const int tid  = threadIdx.x;
    const int t    = blockIdx.x;
    const int warp = tid >> 5;
    const int lane = tid & 31;

    for (int i = tid; i < HH * HOR; i += 256) ows[i] = out_w[i];
    __syncthreads();

    const float* fcb = fc_w + (size_t)t * 512 * HH;
    for (int j = warp; j < 512; j += 8) {
        float4 v = ((const float4*)(fcb + (size_t)j * HH))[lane];
        ((float4*)(rowbuf + warp * 128))[lane] = v;
        __syncwarp();
        if (lane < HOR) {
            const float* rb = rowbuf + warp * 128;
            float acc = 0.0f;
            #pragma unroll 4
            for (int k = 0; k < 128; k++) acc = fmaf(rb[k], ows[k * HOR + lane], acc);
            P[j * HOR + lane] = acc;
        }
        __syncwarp();
    }
    __syncthreads();

    if (warp == 0 && lane < HOR) {
        float acc = 0.0f;
        for (int j = 0; j < 512; j++) acc = fmaf(mlp_b[j], P[j * HOR + lane], acc);
        g_bias_part[t * HOR + lane] = acc;
    }

    const int i  = tid & 127;
    const int p0 = (tid >> 7) * 12;
    float acc[12];
    #pragma unroll
    for (int q = 0; q < 12; q++) acc[q] = 0.0f;
    const float* mw = mlp_w + (size_t)i * 512;
    for (int j = 0; j < 512; j++) {
        float m = mw[j];
        const float* pr = P + j * HOR + p0;
        #pragma unroll
        for (int q = 0; q < 12; q++) acc[q] = fmaf(m, pr[q], acc[q]);
    }
    float* dst = g_W2 + ((size_t)t * HH + i) * HOR + p0;
    #pragma unroll
    for (int q = 0; q < 12; q++) dst[q] = acc[q];
}

// ============================================================================
// Kernel 2: final bias = sum_t bias_part + fc_b@out_w + out_b  (unchanged)
// ============================================================================
__global__ void bias_final_kernel(const float* __restrict__ fc_b,
                                  const float* __restrict__ out_w,
                                  const float* __restrict__ out_b)
{
    int p = threadIdx.x;
    if (p >= HOR) return;
    float s = out_b[p];
    for (int t = 0; t < TT; t++) s += g_bias_part[t * HOR + p];
    for (int o = 0; o < HH; o++) s = fmaf(fc_b[o], out_w[o * HOR + p], s);
    g_final_bias[p] = s;
}

// ============================================================================
// Kernel 3 (v2): gx[t][b][g] = x[b][t][:] @ w_i[:,g] + b[g]
// CTA tile: 64 rows x 384 cols. 4096 CTAs, 256 threads, per-thread 8x12.
// smem: xT [128][68] transposed tile + full w_i.  Bias read from global.
// ============================================================================
#define XT_LD 68
__global__ void __launch_bounds__(256, 1) gx_kernel(
    const float* __restrict__ x,     // [B][T][128]
    const float* __restrict__ w_i,   // [128][384]
    const float* __restrict__ bvec)  // [384]
{
    extern __shared__ float sm[];
    float* xT = sm;                        // 128*68 = 8704 floats
    float* ws = sm + 128 * XT_LD;          // 49152 floats
    const int tid = threadIdx.x;
    const int m0  = blockIdx.x * 64;

    // stage x tile transposed: xT[k][m]  (row = tid>>2, k0 = (tid&3)*32)
    {
        int row = tid >> 2;              // 0..63
        int k0  = (tid & 3) * 32;        // 0,32,64,96
        const float* xrow = x + (size_t)(m0 + row) * INDIM + k0;
        #pragma unroll
        for (int u = 0; u < 8; u++) {
            float4 v = *(const float4*)(xrow + u * 4);
            int k = k0 + u * 4;
            xT[(k + 0) * XT_LD + row] = v.x;
            xT[(k + 1) * XT_LD + row] = v.y;
            xT[(k + 2) * XT_LD + row] = v.z;
            xT[(k + 3) * XT_LD + row] = v.w;
        }
    }
    // stage w_i
    {
        const float4* src = (const float4*)w_i;
        float4* dst = (float4*)ws;
        for (int idx = tid; idx < (128 * GG) / 4; idx += 256) dst[idx] = src[idx];
    }
    __syncthreads();

    // per-thread tile: 8 rows x 12 cols
    const int g0  = (tid & 31) * 12;
    const int mr0 = (tid >> 5) * 8;
    float acc[8][12];
    #pragma unroll
    for (int r = 0; r < 8; r++)
        #pragma unroll
        for (int q = 0; q < 12; q++) acc[r][q] = 0.0f;

    #pragma unroll 2
    for (int k = 0; k < 128; k++) {
        float4 xa = *(const float4*)&xT[k * XT_LD + mr0];
        float4 xb = *(const float4*)&xT[k * XT_LD + mr0 + 4];
        const float* wr = &ws[k * GG + g0];
        float4 w0 = *(const float4*)(wr);
        float4 w1 = *(const float4*)(wr + 4);
        float4 w2 = *(const float4*)(wr + 8);
        float wv[12] = {w0.x,w0.y,w0.z,w0.w, w1.x,w1.y,w1.z,w1.w, w2.x,w2.y,w2.z,w2.w};
        float xr[8]  = {xa.x, xa.y, xa.z, xa.w, xb.x, xb.y, xb.z, xb.w};
        #pragma unroll
        for (int r = 0; r < 8; r++)
            #pragma unroll
            for (int q = 0; q < 12; q++)
                acc[r][q] = fmaf(xr[r], wv[q], acc[r][q]);
    }

    float bsr[12];
    #pragma unroll
    for (int q = 0; q < 12; q++) bsr[q] = __ldg(bvec + g0 + q);

    #pragma unroll
    for (int r = 0; r < 8; r++) {
        int m  = m0 + mr0 + r;
        int bb = m >> 8;         // b
        int tt = m & 255;        // t
        float* dst = g_gx + ((size_t)tt * BB + bb) * GG + g0;
        #pragma unroll
        for (int q = 0; q < 12; q += 4) {
            float4 o;
            o.x = acc[r][q + 0] + bsr[q + 0];
            o.y = acc[r][q + 1] + bsr[q + 1];
            o.z = acc[r][q + 2] + bsr[q + 2];
            o.w = acc[r][q + 3] + bsr[q + 3];
            *(float4*)(dst + q) = o;
        }
    }
}

// ============================================================================
// Kernel 4 (v2): persistent recurrence. 128 CTAs x 512 threads; CTA owns 8
// batch rows for all 256 steps. w_h resident in smem. 2 barriers per step.
// Output projection fused into phase2 as per-thread register accumulators
// (out[r][p] = sum_j sum_t h_t[j,r]*W2_t[j,p]); one deterministic smem
// reduction over j at the very end.
// ============================================================================
__global__ void __launch_bounds__(512, 1) rec_kernel(
    const float* __restrict__ w_h,   // [128][384]
    float* __restrict__ out)         // [1024][24]
{
    extern __shared__ float sm[];
    float* whs = sm;                  // 49152 floats (192 KB)
    float* hT  = whs + 128 * GG;      // [k][r] 128*8
    float* rhT = hT + 1024;           // [k][r]
    float* zs  = rhT + 1024;          // [r][col]

    const int tid = threadIdx.x;
    const int b0  = blockIdx.x * 8;

    {
        const float4* src = (const float4*)w_h;
        float4* dst = (float4*)whs;
        for (int idx = tid; idx < (128 * GG) / 4; idx += 512) dst[idx] = src[idx];
        for (int idx = tid; idx < 1024; idx += 512) hT[idx] = 0.0f;
    }
    __syncthreads();

    // phase-1 identity: 256 cols x 2 row-groups of 4
    const int col = tid & 255;
    const int rh  = (tid >> 8) * 4;        // 0 or 4
    // phase-2 identity: 128 h-indices x 4 row-groups of 2
    const int c2  = tid & 127;
    const int r2  = (tid >> 7) * 2;        // 0,2,4,6

    float oacc[2][24];
    #pragma unroll
    for (int q = 0; q < 2; q++)
        #pragma unroll
        for (int p = 0; p < 24; p++) oacc[q][p] = 0.0f;

    for (int t = 0; t < TT; t++) {
        const float* gxt = g_gx + ((size_t)t * BB + b0) * GG;

        // prefetch phase-1 gx pre-activations (hidden under k-loop)
        float gx1[4];
        #pragma unroll
        for (int u = 0; u < 4; u++) gx1[u] = __ldg(gxt + (rh + u) * GG + col);

        // ---- phase 1: zr pre-activations ----
        float a[4] = {0.0f, 0.0f, 0.0f, 0.0f};
        #pragma unroll 4
        for (int k = 0; k < 128; k++) {
            float4 hv = *(const float4*)&hT[k * 8 + rh];
            float  w  = whs[k * GG + col];
            a[0] = fmaf(hv.x, w, a[0]);
            a[1] = fmaf(hv.y, w, a[1]);
            a[2] = fmaf(hv.z, w, a[2]);
            a[3] = fmaf(hv.w, w, a[3]);
        }
        if (col < 128) {                     // z gate
            #pragma unroll
            for (int u = 0; u < 4; u++)
                zs[(rh + u) * 128 + col] = sigmoid_f(a[u] + gx1[u]);
        } else {                             // r gate -> rh = r .* h
            int j = col - 128;
            #pragma unroll
            for (int u = 0; u < 4; u++) {
                float rv = sigmoid_f(a[u] + gx1[u]);
                rhT[j * 8 + rh + u] = rv * hT[j * 8 + rh + u];
            }
        }
        __syncthreads();

        // ---- phase 2: a = tanh(gx_a + rh @ w_h_a), h update, fused out ----
        // W2 row for this thread's h-index (L2-resident; hidden under k-loop)
        float w2r[24];
        {
            const float4* wp = (const float4*)(g_W2 + ((size_t)t * HH + c2) * HOR);
            #pragma unroll
            for (int u = 0; u < 6; u++) {
                float4 v = __ldg(wp + u);
                w2r[4*u+0] = v.x; w2r[4*u+1] = v.y;
                w2r[4*u+2] = v.z; w2r[4*u+3] = v.w;
            }
        }
        float gx2[2];
        gx2[0] = __ldg(gxt + (r2 + 0) * GG + 256 + c2);
        gx2[1] = __ldg(gxt + (r2 + 1) * GG + 256 + c2);

        float aa[2] = {0.0f, 0.0f};
        #pragma unroll 4
        for (int k = 0; k < 128; k++) {
            float2 rv = *(const float2*)&rhT[k * 8 + r2];
            float  w  = whs[k * GG + 256 + c2];
            aa[0] = fmaf(rv.x, w, aa[0]);
            aa[1] = fmaf(rv.y, w, aa[1]);
        }
        float hn[2];
        #pragma unroll
        for (int q = 0; q < 2; q++) {
            float av   = tanh_f(aa[q] + gx2[q]);
            float z    = zs[(r2 + q) * 128 + c2];
            float hold = hT[c2 * 8 + r2 + q];
            hn[q] = fmaf(z, av - hold, hold);      // (1-z)h + z*a
            hT[c2 * 8 + r2 + q] = hn[q];
        }
        #pragma unroll
        for (int q = 0; q < 2; q++)
            #pragma unroll
            for (int p = 0; p < 24; p++)
                oacc[q][p] = fmaf(hn[q], w2r[p], oacc[q][p]);
        __syncthreads();
    }

    // ---- deterministic output reduction over j (=c2), fixed order ----
    float* part = whs;   // reuse w_h smem (no longer needed): 8*24*128 floats
    #pragma unroll
    for (int q = 0; q < 2; q++)
        #pragma unroll
        for (int p = 0; p < 24; p++)
            part[((r2 + q) * 24 + p) * 128 + c2] = oacc[q][p];
    __syncthreads();

    if (tid < 8 * HOR) {
        int r = tid / HOR;
        int p = tid - r * HOR;
        const float* pp = part + (r * 24 + p) * 128;
        float s = 0.0f;
        for (int c = 0; c < 128; c++) s += pp[c];
        out[(size_t)(b0 + r) * HOR + p] = s + g_final_bias[p];
    }
}

// ============================================================================
// launch
// ============================================================================
extern "C" void kernel_launch(void* const* d_in, const int* in_sizes, int n_in,
                              void* d_out, int out_size)
{
    const float* x     = (const float*)d_in[0];
    const float* w_i   = (const float*)d_in[1];
    const float* w_h   = (const float*)d_in[2];
    const float* bvec  = (const float*)d_in[3];
    const float* mlp_w = (const float*)d_in[4];
    const float* mlp_b = (const float*)d_in[5];
    const float* fc_w  = (const float*)d_in[6];
    const float* fc_b  = (const float*)d_in[7];
    const float* out_w = (const float*)d_in[8];
    const float* out_b = (const float*)d_in[9];
    float* out = (float*)d_out;

    const int smem_w2  = (3072 + 12288 + 1024) * 4;                 // 65536
    const int smem_gx  = (128 * XT_LD + 128 * GG) * 4;              // 231424
    const int smem_rec = (128 * GG + 1024 + 1024 + 1024) * 4;       // 208896

    cudaFuncSetAttribute(w2_kernel,  cudaFuncAttributeMaxDynamicSharedMemorySize, smem_w2);
    cudaFuncSetAttribute(gx_kernel,  cudaFuncAttributeMaxDynamicSharedMemorySize, smem_gx);
    cudaFuncSetAttribute(rec_kernel, cudaFuncAttributeMaxDynamicSharedMemorySize, smem_rec);

    w2_kernel<<<TT, 256, smem_w2>>>(mlp_w, mlp_b, fc_w, out_w);
    bias_final_kernel<<<1, 32>>>(fc_b, out_w, out_b);
    gx_kernel<<<(BB * TT) / 64, 256, smem_gx>>>(x, w_i, bvec);
    rec_kernel<<<BB / 8, 512, smem_rec>>>(w_h, out);
}

// round 4
// speedup vs baseline: 1.6632x; 1.0112x over previous
#include <cuda_runtime.h>
#include <cuda_bf16.h>
#include <cstdint>

// Problem constants (fixed by the dataset)
#define BB   1024
#define TT   256
#define INDIM 128
#define HH   128
#define GG   384      // 3*H
#define HOR  24

// ---------------- scratch (device globals; no allocations allowed) ----------
__device__ float g_gx[(size_t)TT * BB * GG];        // 384 MB: x@w_i + b, layout [t][b][g]
__device__ float g_W2[(size_t)TT * HH * HOR];       // 3 MB:  folded mlp_w@fc_w_t@out_w, [t][i][p]
__device__ float g_bias_part[TT * HOR];             // per-t bias partials (deterministic reduce)
__device__ float g_final_bias[HOR];

// ---------------- packed f32x2 helpers (bit-exact vs 2x fmaf) ----------------
typedef unsigned long long u64;

__device__ __forceinline__ u64 pack2(float lo, float hi) {
    u64 r; asm("mov.b64 %0, {%1, %2};" : "=l"(r) : "f"(lo), "f"(hi)); return r;
}
__device__ __forceinline__ u64 dup2(float v) {
    u64 r; asm("mov.b64 %0, {%1, %1};" : "=l"(r) : "f"(v)); return r;
}
__device__ __forceinline__ void unpack2(u64 v, float& lo, float& hi) {
    asm("mov.b64 {%0, %1}, %2;" : "=f"(lo), "=f"(hi) : "l"(v));
}
__device__ __forceinline__ void ffma2(u64& d, u64 a, u64 b) {
    asm("fma.rn.f32x2 %0, %1, %2, %0;" : "+l"(d) : "l"(a), "l"(b));
}

// ---------------- activation helpers ----------------------------------------
__device__ __forceinline__ float sigmoid_f(float x) {
    return 1.0f / (1.0f + __expf(-x));
}
__device__ __forceinline__ float tanh_f(float x) {
    float ax = fabsf(x);
    float e  = __expf(2.0f * ax);
    float r  = 1.0f - 2.0f / (e + 1.0f);
    return copysignf(r, x);
}

// ============================================================================
// Kernel 1: fold  W2_t = mlp_w @ (fc_w_t @ out_w)   and  bias partial per t.
// ============================================================================
__global__ void __launch_bounds__(256) w2_kernel(
    const float* __restrict__ mlp_w,   // [128,512]
    const float* __restrict__ mlp_b,   // [512]
    const float* __restrict__ fc_w,    // [131072,128]
    const float* __restrict__ out_w)   // [128,24]
{
    extern __shared__ float sm[];
    float* ows    = sm;                 // 128*24 = 3072
    float* P      = sm + 3072;          // 512*24 = 12288
    float* rowbuf = sm + 3072 + 12288;  // 8*128  = 1024
    const int tid  = threadIdx.x;
    const int t    = blockIdx.x;
    const int warp = tid >> 5;
    const int lane = tid & 31;

    for (int i = tid; i < HH * HOR; i += 256) ows[i] = out_w[i];
    __syncthreads();

    const float* fcb = fc_w + (size_t)t * 512 * HH;
    for (int j = warp; j < 512; j += 8) {
        float4 v = ((const float4*)(fcb + (size_t)j * HH))[lane];
        ((float4*)(rowbuf + warp * 128))[lane] = v;
        __syncwarp();
        if (lane < HOR) {
            const float* rb = rowbuf + warp * 128;
            float acc = 0.0f;
            #pragma unroll 4
            for (int k = 0; k < 128; k++) acc = fmaf(rb[k], ows[k * HOR + lane], acc);
            P[j * HOR + lane] = acc;
        }
        __syncwarp();
    }
    __syncthreads();

    if (warp == 0 && lane < HOR) {
        float acc = 0.0f;
        for (int j = 0; j < 512; j++) acc = fmaf(mlp_b[j], P[j * HOR + lane], acc);
        g_bias_part[t * HOR + lane] = acc;
    }

    const int i  = tid & 127;
    const int p0 = (tid >> 7) * 12;
    float acc[12];
    #pragma unroll
    for (int q = 0; q < 12; q++) acc[q] = 0.0f;
    const float* mw = mlp_w + (size_t)i * 512;
    for (int j = 0; j < 512; j++) {
        float m = mw[j];
        const float* pr = P + j * HOR + p0;
        #pragma unroll
        for (int q = 0; q < 12; q++) acc[q] = fmaf(m, pr[q], acc[q]);
    }
    float* dst = g_W2 + ((size_t)t * HH + i) * HOR + p0;
    #pragma unroll
    for (int q = 0; q < 12; q++) dst[q] = acc[q];
}

// ============================================================================
// Kernel 2: final bias = sum_t bias_part + fc_b@out_w + out_b
// ============================================================================
__global__ void bias_final_kernel(const float* __restrict__ fc_b,
                                  const float* __restrict__ out_w,
                                  const float* __restrict__ out_b)
{
    int p = threadIdx.x;
    if (p >= HOR) return;
    float s = out_b[p];
    for (int t = 0; t < TT; t++) s += g_bias_part[t * HOR + p];
    for (int o = 0; o < HH; o++) s = fmaf(fc_b[o], out_w[o * HOR + p], s);
    g_final_bias[p] = s;
}

// ============================================================================
// Kernel 3 (v3): gx = x @ w_i + b, FFMA2 inner loop (pack along gate cols).
// CTA tile: 64 rows x 384 cols. 4096 CTAs, 256 threads, per-thread 8x12.
// ============================================================================
#define XT_LD 68
__global__ void __launch_bounds__(256, 1) gx_kernel(
    const float* __restrict__ x,     // [B][T][128]
    const float* __restrict__ w_i,   // [128][384]
    const float* __restrict__ bvec)  // [384]
{
    extern __shared__ float sm[];
    float* xT = sm;                        // 128*68 floats
    float* ws = sm + 128 * XT_LD;          // 49152 floats
    const int tid = threadIdx.x;
    const int m0  = blockIdx.x * 64;

    // stage x tile transposed: xT[k][m]
    {
        int row = tid >> 2;              // 0..63
        int k0  = (tid & 3) * 32;        // 0,32,64,96
        const float* xrow = x + (size_t)(m0 + row) * INDIM + k0;
        #pragma unroll
        for (int u = 0; u < 8; u++) {
            float4 v = *(const float4*)(xrow + u * 4);
            int k = k0 + u * 4;
            xT[(k + 0) * XT_LD + row] = v.x;
            xT[(k + 1) * XT_LD + row] = v.y;
            xT[(k + 2) * XT_LD + row] = v.z;
            xT[(k + 3) * XT_LD + row] = v.w;
        }
    }
    // stage w_i
    {
        const float4* src = (const float4*)w_i;
        float4* dst = (float4*)ws;
        for (int idx = tid; idx < (128 * GG) / 4; idx += 256) dst[idx] = src[idx];
    }
    __syncthreads();

    // per-thread tile: 8 rows x 12 cols; accumulators packed along q (6 pairs)
    const int g0  = (tid & 31) * 12;     // byte offset g0*4 = multiple of 48 -> 16B aligned
    const int mr0 = (tid >> 5) * 8;
    u64 acc2[8][6];
    #pragma unroll
    for (int r = 0; r < 8; r++)
        #pragma unroll
        for (int q = 0; q < 6; q++) acc2[r][q] = 0ULL;

    #pragma unroll 2
    for (int k = 0; k < 128; k++) {
        float4 xa = *(const float4*)&xT[k * XT_LD + mr0];
        float4 xb = *(const float4*)&xT[k * XT_LD + mr0 + 4];
        const u64* wr = (const u64*)&ws[k * GG + g0];
        ulonglong2 wv0 = *(const ulonglong2*)(wr);       // q pairs (0,1),(2,3)
        ulonglong2 wv1 = *(const ulonglong2*)(wr + 2);   // (4,5),(6,7)
        ulonglong2 wv2 = *(const ulonglong2*)(wr + 4);   // (8,9),(10,11)
        u64 wq[6] = {wv0.x, wv0.y, wv1.x, wv1.y, wv2.x, wv2.y};
        u64 xd[8];
        xd[0] = dup2(xa.x); xd[1] = dup2(xa.y); xd[2] = dup2(xa.z); xd[3] = dup2(xa.w);
        xd[4] = dup2(xb.x); xd[5] = dup2(xb.y); xd[6] = dup2(xb.z); xd[7] = dup2(xb.w);
        #pragma unroll
        for (int r = 0; r < 8; r++)
            #pragma unroll
            for (int q = 0; q < 6; q++)
                ffma2(acc2[r][q], xd[r], wq[q]);
    }

    float bsr[12];
    #pragma unroll
    for (int q = 0; q < 12; q++) bsr[q] = __ldg(bvec + g0 + q);

    #pragma unroll
    for (int r = 0; r < 8; r++) {
        int m  = m0 + mr0 + r;
        int bb = m >> 8;         // b
        int tt = m & 255;        // t
        float* dst = g_gx + ((size_t)tt * BB + bb) * GG + g0;
        float av[12];
        #pragma unroll
        for (int q = 0; q < 6; q++) unpack2(acc2[r][q], av[2*q], av[2*q+1]);
        #pragma unroll
        for (int q = 0; q < 12; q += 4) {
            float4 o;
            o.x = av[q + 0] + bsr[q + 0];
            o.y = av[q + 1] + bsr[q + 1];
            o.z = av[q + 2] + bsr[q + 2];
            o.w = av[q + 3] + bsr[q + 3];
            *(float4*)(dst + q) = o;
        }
    }
}

// ============================================================================
// Kernel 4 (v3): persistent recurrence with FFMA2 (pack along batch rows).
// 128 CTAs x 512 threads; CTA owns 8 batch rows for all 256 steps.
// ============================================================================
__global__ void __launch_bounds__(512, 1) rec_kernel(
    const float* __restrict__ w_h,   // [128][384]
    float* __restrict__ out)         // [1024][24]
{
    extern __shared__ float sm[];
    float* whs = sm;                  // 49152 floats
    float* hT  = whs + 128 * GG;      // [k][r] 128*8
    float* rhT = hT + 1024;           // [k][r]
    float* zs  = rhT + 1024;          // [r][col]

    const int tid = threadIdx.x;
    const int b0  = blockIdx.x * 8;

    {
        const float4* src = (const float4*)w_h;
        float4* dst = (float4*)whs;
        for (int idx = tid; idx < (128 * GG) / 4; idx += 512) dst[idx] = src[idx];
        for (int idx = tid; idx < 1024; idx += 512) hT[idx] = 0.0f;
    }
    __syncthreads();

    // phase-1 identity: 256 cols x 2 row-groups of 4
    const int col = tid & 255;
    const int rh  = (tid >> 8) * 4;        // 0 or 4
    // phase-2 identity: 128 h-indices x 4 row-groups of 2
    const int c2  = tid & 127;
    const int r2  = (tid >> 7) * 2;        // 0,2,4,6

    u64 oacc2[24];                         // packed out accum: rows (r2, r2+1)
    #pragma unroll
    for (int p = 0; p < 24; p++) oacc2[p] = 0ULL;

    for (int t = 0; t < TT; t++) {
        const float* gxt = g_gx + ((size_t)t * BB + b0) * GG;

        // prefetch phase-1 gx pre-activations
        float gx1[4];
        #pragma unroll
        for (int u = 0; u < 4; u++) gx1[u] = __ldg(gxt + (rh + u) * GG + col);

        // ---- phase 1: zr pre-activations (rows packed in pairs) ----
        u64 p1a = 0ULL, p1b = 0ULL;        // pairs (rh,rh+1), (rh+2,rh+3)
        #pragma unroll 4
        for (int k = 0; k < 128; k++) {
            ulonglong2 hv = *(const ulonglong2*)&hT[k * 8 + rh];   // 16B aligned
            u64 wd = dup2(whs[k * GG + col]);
            ffma2(p1a, hv.x, wd);
            ffma2(p1b, hv.y, wd);
        }
        float a[4];
        unpack2(p1a, a[0], a[1]);
        unpack2(p1b, a[2], a[3]);

        if (col < 128) {                     // z gate
            #pragma unroll
            for (int u = 0; u < 4; u++)
                zs[(rh + u) * 128 + col] = sigmoid_f(a[u] + gx1[u]);
        } else {                             // r gate -> rh = r .* h
            int j = col - 128;
            #pragma unroll
            for (int u = 0; u < 4; u++) {
                float rv = sigmoid_f(a[u] + gx1[u]);
                rhT[j * 8 + rh + u] = rv * hT[j * 8 + rh + u];
            }
        }
        __syncthreads();

        // ---- phase 2: a = tanh(gx_a + rh @ w_h_a), h update, fused out ----
        float w2r[24];
        {
            const float4* wp = (const float4*)(g_W2 + ((size_t)t * HH + c2) * HOR);
            #pragma unroll
            for (int u = 0; u < 6; u++) {
                float4 v = __ldg(wp + u);
                w2r[4*u+0] = v.x; w2r[4*u+1] = v.y;
                w2r[4*u+2] = v.z; w2r[4*u+3] = v.w;
            }
        }
        float gx2[2];
        gx2[0] = __ldg(gxt + (r2 + 0) * GG + 256 + c2);
        gx2[1] = __ldg(gxt + (r2 + 1) * GG + 256 + c2);

        u64 aacc = 0ULL;                     // pair (r2, r2+1)
        #pragma unroll 4
        for (int k = 0; k < 128; k++) {
            u64 rv = *(const u64*)&rhT[k * 8 + r2];   // r2 even -> 8B aligned
            u64 wd = dup2(whs[k * GG + 256 + c2]);
            ffma2(aacc, rv, wd);
        }
        float aa[2];
        unpack2(aacc, aa[0], aa[1]);

        float hn[2];
        #pragma unroll
        for (int q = 0; q < 2; q++) {
            float av   = tanh_f(aa[q] + gx2[q]);
            float z    = zs[(r2 + q) * 128 + c2];
            float hold = hT[c2 * 8 + r2 + q];
            hn[q] = fmaf(z, av - hold, hold);      // (1-z)h + z*a
            hT[c2 * 8 + r2 + q] = hn[q];
        }
        u64 hn2 = pack2(hn[0], hn[1]);
        #pragma unroll
        for (int p = 0; p < 24; p++) {
            u64 wd = dup2(w2r[p]);
            ffma2(oacc2[p], hn2, wd);
        }
        __syncthreads();
    }

    // ---- deterministic output reduction over j (=c2), fixed order ----
    float* part = whs;   // reuse w_h smem: 8*24*128 floats fits
    #pragma unroll
    for (int p = 0; p < 24; p++) {
        float v0, v1;
        unpack2(oacc2[p], v0, v1);
        part[((r2 + 0) * 24 + p) * 128 + c2] = v0;
        part[((r2 + 1) * 24 + p) * 128 + c2] = v1;
    }
    __syncthreads();

    if (tid < 8 * HOR) {
        int r = tid / HOR;
        int p = tid - r * HOR;
        const float* pp = part + (r * 24 + p) * 128;
        float s = 0.0f;
        for (int c = 0; c < 128; c++) s += pp[c];
        out[(size_t)(b0 + r) * HOR + p] = s + g_final_bias[p];
    }
}

// ============================================================================
// launch
// ============================================================================
extern "C" void kernel_launch(void* const* d_in, const int* in_sizes, int n_in,
                              void* d_out, int out_size)
{
    const float* x     = (const float*)d_in[0];
    const float* w_i   = (const float*)d_in[1];
    const float* w_h   = (const float*)d_in[2];
    const float* bvec  = (const float*)d_in[3];
    const float* mlp_w = (const float*)d_in[4];
    const float* mlp_b = (const float*)d_in[5];
    const float* fc_w  = (const float*)d_in[6];
    const float* fc_b  = (const float*)d_in[7];
    const float* out_w = (const float*)d_in[8];
    const float* out_b = (const float*)d_in[9];
    float* out = (float*)d_out;

    const int smem_w2  = (3072 + 12288 + 1024) * 4;                 // 65536
    const int smem_gx  = (128 * XT_LD + 128 * GG) * 4;              // 231424
    const int smem_rec = (128 * GG + 1024 + 1024 + 1024) * 4;       // 208896

    cudaFuncSetAttribute(w2_kernel,  cudaFuncAttributeMaxDynamicSharedMemorySize, smem_w2);
    cudaFuncSetAttribute(gx_kernel,  cudaFuncAttributeMaxDynamicSharedMemorySize, smem_gx);
    cudaFuncSetAttribute(rec_kernel, cudaFuncAttributeMaxDynamicSharedMemorySize, smem_rec);

    w2_kernel<<<TT, 256, smem_w2>>>(mlp_w, mlp_b, fc_w, out_w);
    bias_final_kernel<<<1, 32>>>(fc_b, out_w, out_b);
    gx_kernel<<<(BB * TT) / 64, 256, smem_gx>>>(x, w_i, bvec);
    rec_kernel<<<BB / 8, 512, smem_rec>>>(w_h, out);
}